// round 16
// baseline (speedup 1.0000x reference)
#include <cuda_runtime.h>
#include <math.h>

#define B_ 4
#define I_ 512
#define K_ 512
#define C_ 64
#define EPS_LN 1e-5f

// -------- scratch (device globals; allocation is forbidden) --------
__device__ float   g_Qa[B_ * K_ * C_];      // Q @ W1^T + b1
__device__ float   g_R [B_ * K_ * C_];      // Qa / D
__device__ float   g_Va[B_ * I_ * C_];      // contraction result (pre-LN1)
__device__ float   g_Vp[B_ * I_ * C_];      // V + LN1(Va)@W2^T + b2 (pre-LN2)
__device__ double2 g_part1[B_ * I_];        // per-(b,i) {sum,sumsq} of Va
__device__ double2 g_part2[512];            // per-linear2-block {sum,sumsq}

// ---- L2 evict-first policy (z is streamed once per pass; keep it
// ---- out of L2's working set so R/Va/partials stay resident).
__device__ __forceinline__ unsigned long long mk_evict_first_policy() {
    unsigned long long pol;
    asm("createpolicy.fractional.L2::evict_first.b64 %0, 1.0;" : "=l"(pol));
    return pol;
}
__device__ __forceinline__ float4 ldg_ef4(const float4* p,
                                          unsigned long long pol) {
    float4 v;
    asm("ld.global.nc.L2::cache_hint.v4.f32 {%0,%1,%2,%3}, [%4], %5;"
        : "=f"(v.x), "=f"(v.y), "=f"(v.z), "=f"(v.w) : "l"(p), "l"(pol));
    return v;
}

// ---------------------------------------------------------------
// Linear1 (R11-proven, 16 rows/block):
//   Qa[row,c] = b1[c] + sum_j Q[row,j]*W1[c,j]
// ---------------------------------------------------------------
__global__ void __launch_bounds__(256) k_linear1(const float* __restrict__ Q,
                                                 const float* __restrict__ W1,
                                                 const float* __restrict__ b1) {
    __shared__ float Ws[C_][C_ + 1];
    __shared__ float Qs[16][C_];
    int t = threadIdx.x;
    int base = blockIdx.x * 16;
    for (int idx = t; idx < C_ * C_; idx += 256)
        Ws[idx / C_][idx % C_] = W1[idx];
    for (int idx = t; idx < 16 * C_; idx += 256)
        Qs[idx >> 6][idx & 63] = Q[(size_t)(base + (idx >> 6)) * C_ + (idx & 63)];
    __syncthreads();
    int c = t & 63, rg = t >> 6;        // rg in 0..3, rows rg*4..rg*4+3
    float bb = __ldg(&b1[c]);
    float a0 = bb, a1 = bb, a2 = bb, a3 = bb;
#pragma unroll
    for (int j = 0; j < C_; j++) {
        float w = Ws[c][j];
        a0 += Qs[rg * 4 + 0][j] * w;
        a1 += Qs[rg * 4 + 1][j] * w;
        a2 += Qs[rg * 4 + 2][j] * w;
        a3 += Qs[rg * 4 + 3][j] * w;
    }
    g_Qa[(size_t)(base + rg * 4 + 0) * C_ + c] = a0;
    g_Qa[(size_t)(base + rg * 4 + 1) * C_ + c] = a1;
    g_Qa[(size_t)(base + rg * 4 + 2) * C_ + c] = a2;
    g_Qa[(size_t)(base + rg * 4 + 3) * C_ + c] = a3;
}

// ---------------------------------------------------------------
// Deterministic active-index compaction (R2-proven form).
//   WMODE 0 : weight = m + 1e-6            [pass1]
//   WMODE 1 : weight = m * (m + 1e-6)      [pass2]
// ---------------------------------------------------------------
template<int WMODE>
__device__ __forceinline__ int compact_active(const float* __restrict__ mp,
                                              size_t mstride,
                                              int* s_idx, float* s_w,
                                              int* s_cnt, int* s_off) {
    int t = threadIdx.x;
    int lane = t & 31, wid = t >> 5;
    float mv[2]; unsigned bal[2];
#pragma unroll
    for (int q = 0; q < 2; q++) {
        int g = wid + q * 8;
        int i = g * 32 + lane;
        mv[q] = __ldg(&mp[(size_t)i * mstride]);
        bal[q] = __ballot_sync(0xffffffffu, mv[q] != 0.f);
        if (lane == 0) s_cnt[g] = __popc(bal[q]);
    }
    __syncthreads();
    if (t == 0) {
        int acc = 0;
#pragma unroll
        for (int g = 0; g < 16; g++) { s_off[g] = acc; acc += s_cnt[g]; }
        s_off[16] = acc;
    }
    __syncthreads();
#pragma unroll
    for (int q = 0; q < 2; q++) {
        int g = wid + q * 8;
        int i = g * 32 + lane;
        if (mv[q] != 0.f) {
            int pos = s_off[g] + __popc(bal[q] & ((1u << lane) - 1u));
            s_idx[pos] = i;
            s_w[pos] = (WMODE == 0) ? (mv[q] + 1e-6f)
                                    : (mv[q] * (mv[q] + 1e-6f));
        }
    }
    __syncthreads();
    return s_off[16];
}

// ---------------------------------------------------------------
// Pass 1 (R15-proven): per (b,k):
//   D[c] = sum_{active i} exp(z[b,i,k,c]) * (m+1e-6)
//   R[b,k,c] = Qa[b,k,c] / D[c]
// ---------------------------------------------------------------
__global__ void __launch_bounds__(256, 8)
k_pass1(const float* __restrict__ z, const float* __restrict__ zm) {
    int k = blockIdx.x, b = blockIdx.y;
    int t = threadIdx.x;
    __shared__ int    s_idx[I_];
    __shared__ float  s_w[I_];
    __shared__ int    s_cnt[16];
    __shared__ int    s_off[17];
    __shared__ float4 red[16][16];

    const float* mp = zm + (size_t)b * I_ * K_ + k;
    int nact = compact_active<0>(mp, K_, s_idx, s_w, s_cnt, s_off);

    unsigned long long pol = mk_evict_first_policy();
    int c4 = t & 15;        // float4 channel group
    int di = t >> 4;        // row lane
    const float4* zb = (const float4*)z
        + (((size_t)b * I_) * K_ + k) * (C_ / 4) + c4;
    const size_t zstride = (size_t)K_ * (C_ / 4);

    float4 acc = make_float4(0.f, 0.f, 0.f, 0.f);
#pragma unroll 4
    for (int j = di; j < nact; j += 16) {
        int i = s_idx[j];
        float w = s_w[j];
        float4 zv = ldg_ef4(&zb[(size_t)i * zstride], pol);
        acc.x += __expf(zv.x) * w;
        acc.y += __expf(zv.y) * w;
        acc.z += __expf(zv.z) * w;
        acc.w += __expf(zv.w) * w;
    }
    red[di][c4] = acc;
    __syncthreads();
    if (t < 16) {
        float4 D = red[0][t];
#pragma unroll
        for (int r = 1; r < 16; r++) {
            float4 v = red[r][t];
            D.x += v.x; D.y += v.y; D.z += v.z; D.w += v.w;
        }
        size_t off = ((size_t)b * K_ + k) * (C_ / 4) + t;
        float4 qa = ((const float4*)g_Qa)[off];
        float4 R = make_float4(qa.x / D.x, qa.y / D.y,
                               qa.z / D.z, qa.w / D.w);
        ((float4*)g_R)[off] = R;
    }
}

// ---------------------------------------------------------------
// Pass 2 (R15-proven body; launched as two half-grids so a z-pass
// lands on the ncu capture slot): per (b,i):
//   Va[b,i,c] = sum_{active k} m*(m+1e-6) * exp(z[b,i,k,c]) * R[b,k,c]
// ---------------------------------------------------------------
__global__ void __launch_bounds__(256, 8)
k_pass2(const float* __restrict__ z, const float* __restrict__ zm, int b0) {
    int i = blockIdx.x, b = b0 + blockIdx.y;
    int t = threadIdx.x;
    __shared__ int    s_idx[K_];
    __shared__ float  s_w[K_];
    __shared__ int    s_cnt[16];
    __shared__ int    s_off[17];
    __shared__ float4 red[16][16];
    __shared__ double sd[16], sd2[16];

    const float* mp = zm + ((size_t)b * I_ + i) * K_;
    int nact = compact_active<1>(mp, 1, s_idx, s_w, s_cnt, s_off);

    unsigned long long pol = mk_evict_first_policy();
    int c4 = t & 15;
    int dk = t >> 4;
    const float4* zb = (const float4*)z
        + (((size_t)b * I_ + i) * K_) * (C_ / 4) + c4;
    const float4* Rb = (const float4*)g_R + ((size_t)b * K_) * (C_ / 4) + c4;

    float4 acc = make_float4(0.f, 0.f, 0.f, 0.f);
#pragma unroll 4
    for (int j = dk; j < nact; j += 16) {
        int kk = s_idx[j];
        float w = s_w[j];
        float4 zv = ldg_ef4(&zb[(size_t)kk * (C_ / 4)], pol);
        float4 Rv = __ldg(&Rb[(size_t)kk * (C_ / 4)]);
        acc.x += w * __expf(zv.x) * Rv.x;
        acc.y += w * __expf(zv.y) * Rv.y;
        acc.z += w * __expf(zv.z) * Rv.z;
        acc.w += w * __expf(zv.w) * Rv.w;
    }
    red[dk][c4] = acc;
    __syncthreads();
    if (t < 16) {
        float4 v = red[0][t];
#pragma unroll
        for (int r = 1; r < 16; r++) {
            float4 u = red[r][t];
            v.x += u.x; v.y += u.y; v.z += u.z; v.w += u.w;
        }
        ((float4*)g_Va)[((size_t)b * I_ + i) * (C_ / 4) + t] = v;
        sd [t] = (double)v.x + (double)v.y + (double)v.z + (double)v.w;
        sd2[t] = (double)v.x * v.x + (double)v.y * v.y
               + (double)v.z * v.z + (double)v.w * v.w;
    }
    __syncthreads();
    if (t == 0) {
        double s = 0.0, s2 = 0.0;
#pragma unroll
        for (int r = 0; r < 16; r++) { s += sd[r]; s2 += sd2[r]; }
        g_part1[(size_t)b * I_ + i] = make_double2(s, s2);
    }
}

// ---------------------------------------------------------------
// Linear2 (4 rows/block, grid 512, one output/thread, shuffle stats):
//   every block redundantly reduces its batch's 512 LN1 partials
//   via warp shuffles (fixed order), then Vp = V + LN1(Va)@W2^T + b2.
//   Emits per-block LN2 partials.
// ---------------------------------------------------------------
__global__ void __launch_bounds__(256) k_linear2(const float* __restrict__ V,
                                                 const float* __restrict__ W2,
                                                 const float* __restrict__ b2) {
    __shared__ float  Ws[C_][C_ + 1];
    __shared__ float  Xs[4][C_];
    __shared__ double swp[8][2];
    __shared__ float  s_mu, s_rs;
    int t = threadIdx.x;
    int lane = t & 31, wid = t >> 5;
    int base = blockIdx.x * 4;
    int b = blockIdx.x >> 7;            // 128 blocks per batch

    // inline LN1-stat reduce: 512 partials, 2 per thread, shuffles only
    {
        const double2* p = g_part1 + (size_t)b * I_;
        double2 v0 = p[t], v1 = p[t + 256];
        double s = v0.x + v1.x, s2 = v0.y + v1.y;
#pragma unroll
        for (int o = 16; o > 0; o >>= 1) {
            s  += __shfl_down_sync(0xffffffffu, s,  o);
            s2 += __shfl_down_sync(0xffffffffu, s2, o);
        }
        if (lane == 0) { swp[wid][0] = s; swp[wid][1] = s2; }
        __syncthreads();
        if (t == 0) {
            double ts = 0.0, ts2 = 0.0;
#pragma unroll
            for (int w = 0; w < 8; w++) { ts += swp[w][0]; ts2 += swp[w][1]; }
            const double N = (double)(I_ * C_);
            double mu  = ts / N;
            double var = ts2 / N - mu * mu;
            s_mu = (float)mu;
            s_rs = (float)(1.0 / sqrt(var + (double)EPS_LN));
        }
    }

    for (int idx = t; idx < C_ * C_; idx += 256)
        Ws[idx / C_][idx % C_] = W2[idx];
    // Xs needs s_mu: the __syncthreads below orders it after t==0's write
    __syncthreads();
    float mu = s_mu, rs = s_rs;
    if (t < 4 * C_)
        Xs[t >> 6][t & 63] =
            (g_Va[(size_t)(base + (t >> 6)) * C_ + (t & 63)] - mu) * rs;
    __syncthreads();
    int c = t & 63, r = t >> 6;         // one output per thread
    float acc = __ldg(&b2[c]);
#pragma unroll
    for (int j = 0; j < C_; j++)
        acc += Xs[r][j] * Ws[c][j];
    size_t off = (size_t)(base + r) * C_ + c;
    float v = __ldg(&V[off]) + acc;
    g_Vp[off] = v;

    double s = (double)v, s2 = (double)v * (double)v;
#pragma unroll
    for (int o = 16; o > 0; o >>= 1) {
        s  += __shfl_down_sync(0xffffffffu, s,  o);
        s2 += __shfl_down_sync(0xffffffffu, s2, o);
    }
    __syncthreads();                    // re-use swp safely
    if (lane == 0) { swp[wid][0] = s; swp[wid][1] = s2; }
    __syncthreads();
    if (t == 0) {
        double ts = 0.0, ts2 = 0.0;
#pragma unroll
        for (int w = 0; w < 8; w++) { ts += swp[w][0]; ts2 += swp[w][1]; }
        g_part2[blockIdx.x] = make_double2(ts, ts2);
    }
}

// ---------------------------------------------------------------
// Final (+ inline LN2-stat reduce): out = (Vp - mean2[b]) * rstd2[b]
// Warp 0 reduces the batch's 128 partials (fixed order).
// ---------------------------------------------------------------
__global__ void __launch_bounds__(256) k_final(float* __restrict__ out) {
    __shared__ float s_mu, s_rs;
    int t = threadIdx.x;
    int b = blockIdx.x >> 7;            // 128 blocks per batch
    if (t < 32) {
        double s = 0.0, s2 = 0.0;
#pragma unroll
        for (int q = 0; q < 4; q++) {
            double2 p = g_part2[b * 128 + q * 32 + t];
            s += p.x; s2 += p.y;
        }
#pragma unroll
        for (int o = 16; o > 0; o >>= 1) {
            s  += __shfl_down_sync(0xffffffffu, s,  o);
            s2 += __shfl_down_sync(0xffffffffu, s2, o);
        }
        if (t == 0) {
            const double N = (double)(I_ * C_);
            double mu  = s / N;
            double var = s2 / N - mu * mu;
            s_mu = (float)mu;
            s_rs = (float)(1.0 / sqrt(var + (double)EPS_LN));
        }
    }
    __syncthreads();
    int idx = blockIdx.x * 256 + t;
    out[idx] = (g_Vp[idx] - s_mu) * s_rs;
}

// ---------------------------------------------------------------
extern "C" void kernel_launch(void* const* d_in, const int* in_sizes, int n_in,
                              void* d_out, int out_size) {
    const float* V  = (const float*)d_in[0];
    const float* Q  = (const float*)d_in[1];
    const float* z  = (const float*)d_in[2];
    const float* zm = (const float*)d_in[3];
    const float* W1 = (const float*)d_in[4];
    const float* b1 = (const float*)d_in[5];
    const float* W2 = (const float*)d_in[6];
    const float* b2 = (const float*)d_in[7];
    float* out = (float*)d_out;

    k_linear1<<<(B_ * K_) / 16, 256>>>(Q, W1, b1);       // 1
    k_pass1  <<<dim3(K_, B_), 256>>>(z, zm);             // 2
    k_pass2  <<<dim3(I_, 2), 256>>>(z, zm, 0);           // 3
    k_pass2  <<<dim3(I_, 2), 256>>>(z, zm, 2);           // 4
    k_linear2<<<(B_ * I_) / 4, 256>>>(V, W2, b2);        // 5
    k_final  <<<(B_ * I_ * C_) / 256, 256>>>(out);       // 6
}

// round 17
// speedup vs baseline: 1.0319x; 1.0319x over previous
#include <cuda_runtime.h>
#include <math.h>

#define B_ 4
#define I_ 512
#define K_ 512
#define C_ 64
#define EPS_LN 1e-5f

// -------- scratch (device globals; allocation is forbidden) --------
__device__ float   g_Qa[B_ * K_ * C_];      // Q @ W1^T + b1
__device__ float   g_R [B_ * K_ * C_];      // Qa / D
__device__ float   g_Va[B_ * I_ * C_];      // contraction result (pre-LN1)
__device__ float   g_Vp[B_ * I_ * C_];      // V + LN1(Va)@W2^T + b2 (pre-LN2)
__device__ double2 g_part1[B_ * I_];        // per-(b,i) {sum,sumsq} of Va
__device__ double2 g_part2[256];            // per-linear2-block {sum,sumsq}

// ---- L2 evict-first policy (z is streamed once per pass; keep it
// ---- out of L2's working set so R/Va/partials stay resident).
__device__ __forceinline__ unsigned long long mk_evict_first_policy() {
    unsigned long long pol;
    asm("createpolicy.fractional.L2::evict_first.b64 %0, 1.0;" : "=l"(pol));
    return pol;
}
__device__ __forceinline__ float4 ldg_ef4(const void* p,
                                          unsigned long long pol) {
    float4 v;
    asm("ld.global.nc.L2::cache_hint.v4.f32 {%0,%1,%2,%3}, [%4], %5;"
        : "=f"(v.x), "=f"(v.y), "=f"(v.z), "=f"(v.w) : "l"(p), "l"(pol));
    return v;
}

// ---------------------------------------------------------------
// Linear1 (R11-proven, 16 rows/block):
//   Qa[row,c] = b1[c] + sum_j Q[row,j]*W1[c,j]
// ---------------------------------------------------------------
__global__ void __launch_bounds__(256) k_linear1(const float* __restrict__ Q,
                                                 const float* __restrict__ W1,
                                                 const float* __restrict__ b1) {
    __shared__ float Ws[C_][C_ + 1];
    __shared__ float Qs[16][C_];
    int t = threadIdx.x;
    int base = blockIdx.x * 16;
    for (int idx = t; idx < C_ * C_; idx += 256)
        Ws[idx / C_][idx % C_] = W1[idx];
    for (int idx = t; idx < 16 * C_; idx += 256)
        Qs[idx >> 6][idx & 63] = Q[(size_t)(base + (idx >> 6)) * C_ + (idx & 63)];
    __syncthreads();
    int c = t & 63, rg = t >> 6;        // rg in 0..3, rows rg*4..rg*4+3
    float bb = __ldg(&b1[c]);
    float a0 = bb, a1 = bb, a2 = bb, a3 = bb;
#pragma unroll
    for (int j = 0; j < C_; j++) {
        float w = Ws[c][j];
        a0 += Qs[rg * 4 + 0][j] * w;
        a1 += Qs[rg * 4 + 1][j] * w;
        a2 += Qs[rg * 4 + 2][j] * w;
        a3 += Qs[rg * 4 + 3][j] * w;
    }
    g_Qa[(size_t)(base + rg * 4 + 0) * C_ + c] = a0;
    g_Qa[(size_t)(base + rg * 4 + 1) * C_ + c] = a1;
    g_Qa[(size_t)(base + rg * 4 + 2) * C_ + c] = a2;
    g_Qa[(size_t)(base + rg * 4 + 3) * C_ + c] = a3;
}

// ---------------------------------------------------------------
// Deterministic active-index compaction, PACKED form:
//   s_iw[pos] = { weight, bitcast(byte_offset = idx * offmul) }
// One LDS.64 per loop iteration instead of two LDS.32; address
// becomes base + off (single IADD, no IMAD.WIDE chain).
//   WMODE 0 : weight = m + 1e-6            [pass1]
//   WMODE 1 : weight = m * (m + 1e-6)      [pass2]
// ---------------------------------------------------------------
template<int WMODE>
__device__ __forceinline__ int compact_active(const float* __restrict__ mp,
                                              size_t mstride, int offmul,
                                              float2* s_iw,
                                              int* s_cnt, int* s_off) {
    int t = threadIdx.x;
    int lane = t & 31, wid = t >> 5;
    float mv[2]; unsigned bal[2];
#pragma unroll
    for (int q = 0; q < 2; q++) {
        int g = wid + q * 8;
        int i = g * 32 + lane;
        mv[q] = __ldg(&mp[(size_t)i * mstride]);
        bal[q] = __ballot_sync(0xffffffffu, mv[q] != 0.f);
        if (lane == 0) s_cnt[g] = __popc(bal[q]);
    }
    __syncthreads();
    if (t == 0) {
        int acc = 0;
#pragma unroll
        for (int g = 0; g < 16; g++) { s_off[g] = acc; acc += s_cnt[g]; }
        s_off[16] = acc;
    }
    __syncthreads();
#pragma unroll
    for (int q = 0; q < 2; q++) {
        int g = wid + q * 8;
        int i = g * 32 + lane;
        if (mv[q] != 0.f) {
            int pos = s_off[g] + __popc(bal[q] & ((1u << lane) - 1u));
            float w = (WMODE == 0) ? (mv[q] + 1e-6f)
                                   : (mv[q] * (mv[q] + 1e-6f));
            s_iw[pos] = make_float2(w, __int_as_float(i * offmul));
        }
    }
    __syncthreads();
    return s_off[16];
}

// ---------------------------------------------------------------
// Pass 1 (R15 body + packed compaction): per (b,k):
//   D[c] = sum_{active i} exp(z[b,i,k,c]) * (m+1e-6)
//   R[b,k,c] = Qa[b,k,c] / D[c]
// ---------------------------------------------------------------
__global__ void __launch_bounds__(256, 8)
k_pass1(const float* __restrict__ z, const float* __restrict__ zm) {
    int k = blockIdx.x, b = blockIdx.y;
    int t = threadIdx.x;
    __shared__ float2 s_iw[I_];
    __shared__ int    s_cnt[16];
    __shared__ int    s_off[17];
    __shared__ float4 red[16][16];

    const float* mp = zm + (size_t)b * I_ * K_ + k;
    int nact = compact_active<0>(mp, K_, K_ * C_ * 4, s_iw, s_cnt, s_off);

    unsigned long long pol = mk_evict_first_policy();
    int c4 = t & 15;        // float4 channel group
    int di = t >> 4;        // row lane
    const char* zb = (const char*)z
        + ((size_t)b * I_ * K_ + (size_t)k) * (C_ * 4) + c4 * 16;

    float4 acc = make_float4(0.f, 0.f, 0.f, 0.f);
#pragma unroll 4
    for (int j = di; j < nact; j += 16) {
        float2 iw = s_iw[j];
        float4 zv = ldg_ef4(zb + (size_t)(unsigned)__float_as_int(iw.y), pol);
        acc.x += __expf(zv.x) * iw.x;
        acc.y += __expf(zv.y) * iw.x;
        acc.z += __expf(zv.z) * iw.x;
        acc.w += __expf(zv.w) * iw.x;
    }
    red[di][c4] = acc;
    __syncthreads();
    if (t < 16) {
        float4 D = red[0][t];
#pragma unroll
        for (int r = 1; r < 16; r++) {
            float4 v = red[r][t];
            D.x += v.x; D.y += v.y; D.z += v.z; D.w += v.w;
        }
        size_t off = ((size_t)b * K_ + k) * (C_ / 4) + t;
        float4 qa = ((const float4*)g_Qa)[off];
        float4 R = make_float4(qa.x / D.x, qa.y / D.y,
                               qa.z / D.z, qa.w / D.w);
        ((float4*)g_R)[off] = R;
    }
}

// ---------------------------------------------------------------
// Pass 2 (R15 body + packed compaction): per (b,i):
//   Va[b,i,c] = sum_{active k} m*(m+1e-6) * exp(z[b,i,k,c]) * R[b,k,c]
// Same byte offset serves both z and R (both 256B per k-row).
// ---------------------------------------------------------------
__global__ void __launch_bounds__(256, 8)
k_pass2(const float* __restrict__ z, const float* __restrict__ zm) {
    int i = blockIdx.x, b = blockIdx.y;
    int t = threadIdx.x;
    __shared__ float2 s_iw[K_];
    __shared__ int    s_cnt[16];
    __shared__ int    s_off[17];
    __shared__ float4 red[16][16];
    __shared__ double sd[16], sd2[16];

    const float* mp = zm + ((size_t)b * I_ + i) * K_;
    int nact = compact_active<1>(mp, 1, C_ * 4, s_iw, s_cnt, s_off);

    unsigned long long pol = mk_evict_first_policy();
    int c4 = t & 15;
    int dk = t >> 4;
    const char* zb = (const char*)z
        + ((size_t)b * I_ + i) * (size_t)(K_ * C_ * 4) + c4 * 16;
    const char* Rb = (const char*)g_R + (size_t)b * (K_ * C_ * 4) + c4 * 16;

    float4 acc = make_float4(0.f, 0.f, 0.f, 0.f);
#pragma unroll 4
    for (int j = dk; j < nact; j += 16) {
        float2 iw = s_iw[j];
        size_t off = (size_t)(unsigned)__float_as_int(iw.y);
        float4 zv = ldg_ef4(zb + off, pol);
        float4 Rv = __ldg((const float4*)(Rb + off));
        acc.x += iw.x * __expf(zv.x) * Rv.x;
        acc.y += iw.x * __expf(zv.y) * Rv.y;
        acc.z += iw.x * __expf(zv.z) * Rv.z;
        acc.w += iw.x * __expf(zv.w) * Rv.w;
    }
    red[dk][c4] = acc;
    __syncthreads();
    if (t < 16) {
        float4 v = red[0][t];
#pragma unroll
        for (int r = 1; r < 16; r++) {
            float4 u = red[r][t];
            v.x += u.x; v.y += u.y; v.z += u.z; v.w += u.w;
        }
        ((float4*)g_Va)[((size_t)b * I_ + i) * (C_ / 4) + t] = v;
        sd [t] = (double)v.x + (double)v.y + (double)v.z + (double)v.w;
        sd2[t] = (double)v.x * v.x + (double)v.y * v.y
               + (double)v.z * v.z + (double)v.w * v.w;
    }
    __syncthreads();
    if (t == 0) {
        double s = 0.0, s2 = 0.0;
#pragma unroll
        for (int r = 0; r < 16; r++) { s += sd[r]; s2 += sd2[r]; }
        g_part1[(size_t)b * I_ + i] = make_double2(s, s2);
    }
}

// ---------------------------------------------------------------
// Linear2 (R15-proven: 8 rows/block, grid 256, shuffle stats):
//   every block redundantly reduces its batch's 512 LN1 partials
//   via warp shuffles (fixed order), then Vp = V + LN1(Va)@W2^T + b2.
//   Emits per-block LN2 partials.
// ---------------------------------------------------------------
__global__ void __launch_bounds__(256) k_linear2(const float* __restrict__ V,
                                                 const float* __restrict__ W2,
                                                 const float* __restrict__ b2) {
    __shared__ float  Ws[C_][C_ + 1];
    __shared__ float  Xs[8][C_];
    __shared__ double swp[8][2];
    __shared__ float  s_mu, s_rs;
    int t = threadIdx.x;
    int lane = t & 31, wid = t >> 5;
    int base = blockIdx.x * 8;
    int b = blockIdx.x >> 6;            // 64 blocks per batch

    // inline LN1-stat reduce: 512 partials, 2 per thread, shuffles only
    {
        const double2* p = g_part1 + (size_t)b * I_;
        double2 v0 = p[t], v1 = p[t + 256];
        double s = v0.x + v1.x, s2 = v0.y + v1.y;
#pragma unroll
        for (int o = 16; o > 0; o >>= 1) {
            s  += __shfl_down_sync(0xffffffffu, s,  o);
            s2 += __shfl_down_sync(0xffffffffu, s2, o);
        }
        if (lane == 0) { swp[wid][0] = s; swp[wid][1] = s2; }
        __syncthreads();
        if (t == 0) {
            double ts = 0.0, ts2 = 0.0;
#pragma unroll
            for (int w = 0; w < 8; w++) { ts += swp[w][0]; ts2 += swp[w][1]; }
            const double N = (double)(I_ * C_);
            double mu  = ts / N;
            double var = ts2 / N - mu * mu;
            s_mu = (float)mu;
            s_rs = (float)(1.0 / sqrt(var + (double)EPS_LN));
        }
    }

    for (int idx = t; idx < C_ * C_; idx += 256)
        Ws[idx / C_][idx % C_] = W2[idx];
    // Xs needs s_mu: the __syncthreads below orders it after t==0's write
    __syncthreads();
    float mu = s_mu, rs = s_rs;
    for (int idx = t; idx < 8 * C_; idx += 256)
        Xs[idx >> 6][idx & 63] =
            (g_Va[(size_t)(base + (idx >> 6)) * C_ + (idx & 63)] - mu) * rs;
    __syncthreads();
    int c = t & 63, rg = t >> 6;        // rows rg*2, rg*2+1
    float bb = __ldg(&b2[c]);
    float a0 = bb, a1 = bb;
#pragma unroll
    for (int j = 0; j < C_; j++) {
        float w = Ws[c][j];
        a0 += Xs[rg * 2 + 0][j] * w;
        a1 += Xs[rg * 2 + 1][j] * w;
    }
    double s = 0.0, s2 = 0.0;
    float av[2] = {a0, a1};
#pragma unroll
    for (int q = 0; q < 2; q++) {
        size_t off = (size_t)(base + rg * 2 + q) * C_ + c;
        float v = __ldg(&V[off]) + av[q];
        g_Vp[off] = v;
        s  += (double)v;
        s2 += (double)v * (double)v;
    }
#pragma unroll
    for (int o = 16; o > 0; o >>= 1) {
        s  += __shfl_down_sync(0xffffffffu, s,  o);
        s2 += __shfl_down_sync(0xffffffffu, s2, o);
    }
    __syncthreads();                    // re-use swp safely
    if (lane == 0) { swp[wid][0] = s; swp[wid][1] = s2; }
    __syncthreads();
    if (t == 0) {
        double ts = 0.0, ts2 = 0.0;
#pragma unroll
        for (int w = 0; w < 8; w++) { ts += swp[w][0]; ts2 += swp[w][1]; }
        g_part2[blockIdx.x] = make_double2(ts, ts2);
    }
}

// ---------------------------------------------------------------
// Final (+ inline LN2-stat reduce): out = (Vp - mean2[b]) * rstd2[b]
// Warp 0 reduces the batch's 64 partials (fixed order).
// ---------------------------------------------------------------
__global__ void __launch_bounds__(256) k_final(float* __restrict__ out) {
    __shared__ float s_mu, s_rs;
    int t = threadIdx.x;
    int b = blockIdx.x >> 7;            // 128 blocks per batch
    if (t < 32) {
        double2 pa = g_part2[b * 64 + t];
        double2 pb = g_part2[b * 64 + 32 + t];
        double s = pa.x + pb.x, s2 = pa.y + pb.y;
#pragma unroll
        for (int o = 16; o > 0; o >>= 1) {
            s  += __shfl_down_sync(0xffffffffu, s,  o);
            s2 += __shfl_down_sync(0xffffffffu, s2, o);
        }
        if (t == 0) {
            const double N = (double)(I_ * C_);
            double mu  = s / N;
            double var = s2 / N - mu * mu;
            s_mu = (float)mu;
            s_rs = (float)(1.0 / sqrt(var + (double)EPS_LN));
        }
    }
    __syncthreads();
    int idx = blockIdx.x * 256 + t;
    out[idx] = (g_Vp[idx] - s_mu) * s_rs;
}

// ---------------------------------------------------------------
extern "C" void kernel_launch(void* const* d_in, const int* in_sizes, int n_in,
                              void* d_out, int out_size) {
    const float* V  = (const float*)d_in[0];
    const float* Q  = (const float*)d_in[1];
    const float* z  = (const float*)d_in[2];
    const float* zm = (const float*)d_in[3];
    const float* W1 = (const float*)d_in[4];
    const float* b1 = (const float*)d_in[5];
    const float* W2 = (const float*)d_in[6];
    const float* b2 = (const float*)d_in[7];
    float* out = (float*)d_out;

    k_linear1<<<(B_ * K_) / 16, 256>>>(Q, W1, b1);
    k_pass1  <<<dim3(K_, B_), 256>>>(z, zm);
    k_pass2  <<<dim3(I_, B_), 256>>>(z, zm);
    k_linear2<<<(B_ * I_) / 8, 256>>>(V, W2, b2);
    k_final  <<<(B_ * I_ * C_) / 256, 256>>>(out);
}